// round 2
// baseline (speedup 1.0000x reference)
#include <cuda_runtime.h>
#include <cstdint>

#define BATCH 32
#define TT 1024
#define DKK 64
#define QT 32          // queries per block
#define KC 128         // k chunk
#define NTH 256

#define SSTR 1032      // scores row stride (floats)
#define KSTR 132       // transposed K stage stride
#define VSTR 68        // V stage stride
#define QSTR 36        // transposed Q stage stride

#define SC_FLOATS (QT * SSTR)            // 33024
#define ST_OFF    SC_FLOATS
#define ST_FLOATS 8704                   // max(64*132=8448, 128*68=8704)
#define QS_OFF    (ST_OFF + ST_FLOATS)   // 41728
#define QS_FLOATS (DKK * QSTR)           // 2304
#define SMEM_FLOATS (QS_OFF + QS_FLOATS) // 44032
#define SMEM_BYTES  (SMEM_FLOATS * 4)    // 176128

#define RES_FLOATS ((size_t)BATCH * TT * DKK)  // 2097152
#define MASK_FILL_F (-4294967296.0f)           // float32(-2^32+1)

__global__ void __launch_bounds__(NTH, 1)
mha_kernel(const float* __restrict__ Kg,
           const float* __restrict__ Vg,
           const float* __restrict__ Qg,
           const unsigned int* __restrict__ Mg,   // bool materialized as 4-byte (int32 or f32): nonzero bits == True
           const float* __restrict__ QMg,
           float* __restrict__ out)
{
    extern __shared__ float sm[];
    float* sc = sm;             // scores [QT][SSTR]
    float* st = sm + ST_OFF;    // K/V staging
    float* qs = sm + QS_OFF;    // Q transposed [d][q]

    const int tid = threadIdx.x;
    const int b   = blockIdx.x / (TT / QT);
    const int qt  = blockIdx.x % (TT / QT);
    const int q0g = qt * QT;

    const float* Qb = Qg + ((size_t)b * TT + q0g) * DKK;
    const float* Kb = Kg + (size_t)b * TT * DKK;
    const float* Vb = Vg + (size_t)b * TT * DKK;

    // ---- stage Q transposed: qs[d*QSTR + q] ----
    for (int idx = tid; idx < QT * DKK; idx += NTH) {
        int q = idx / DKK, d = idx % DKK;
        qs[d * QSTR + q] = Qb[idx];
    }

    const int tx = tid & 31, ty = tid >> 5;
    const int qa = ty * 4;   // phase-A q base (0..28)
    const int ka = tx * 4;   // phase-A k base within chunk (0..124)

    // ================= Phase A: scores = (Q K^T) * 1/sqrt(DK) =================
    for (int kb = 0; kb < TT / KC; ++kb) {
        __syncthreads();
        const float* Kc = Kb + (size_t)kb * KC * DKK;
        for (int idx = tid; idx < KC * DKK; idx += NTH) {
            int k = idx / DKK, d = idx % DKK;
            st[d * KSTR + k] = Kc[idx];      // transpose to [d][k]
        }
        __syncthreads();

        float acc[4][4] = {};
        #pragma unroll
        for (int d = 0; d < DKK; ++d) {
            float4 a  = *(const float4*)&qs[d * QSTR + qa];
            float4 bv = *(const float4*)&st[d * KSTR + ka];
            acc[0][0] += a.x * bv.x; acc[0][1] += a.x * bv.y; acc[0][2] += a.x * bv.z; acc[0][3] += a.x * bv.w;
            acc[1][0] += a.y * bv.x; acc[1][1] += a.y * bv.y; acc[1][2] += a.y * bv.z; acc[1][3] += a.y * bv.w;
            acc[2][0] += a.z * bv.x; acc[2][1] += a.z * bv.y; acc[2][2] += a.z * bv.z; acc[2][3] += a.z * bv.w;
            acc[3][0] += a.w * bv.x; acc[3][1] += a.w * bv.y; acc[3][2] += a.w * bv.z; acc[3][3] += a.w * bv.w;
        }
        #pragma unroll
        for (int i = 0; i < 4; ++i) {
            float4 w = make_float4(acc[i][0] * 0.125f, acc[i][1] * 0.125f,
                                   acc[i][2] * 0.125f, acc[i][3] * 0.125f);
            *(float4*)&sc[(qa + i) * SSTR + kb * KC + ka] = w;
        }
    }
    __syncthreads();

    // ================= Phase B: mask + softmax + query_mask, write attn =======
    {
        const int w = ty, lane = tx;
        #pragma unroll
        for (int r = 0; r < 4; ++r) {
            const int q  = w * 4 + r;
            const int qg = q0g + q;
            const unsigned int* mrow = Mg + ((size_t)b * TT + qg) * (size_t)TT;
            float* srow = sc + q * SSTR;

            float mx = -3.402823466e38f;
            for (int k = lane; k < TT; k += 32) {
                float s = srow[k];
                if (mrow[k] != 0u) s = MASK_FILL_F;   // True -> fill
                srow[k] = s;
                mx = fmaxf(mx, s);
            }
            #pragma unroll
            for (int o = 16; o; o >>= 1) mx = fmaxf(mx, __shfl_xor_sync(0xffffffffu, mx, o));

            float sum = 0.f;
            for (int k = lane; k < TT; k += 32) {
                float e = __expf(srow[k] - mx);
                srow[k] = e;
                sum += e;
            }
            #pragma unroll
            for (int o = 16; o; o >>= 1) sum += __shfl_xor_sync(0xffffffffu, sum, o);

            const float inv = QMg[(size_t)b * TT + qg] / sum;
            float* arow = out + RES_FLOATS + ((size_t)b * TT + qg) * (size_t)TT;
            for (int k = lane; k < TT; k += 32) {
                float v = srow[k] * inv;
                srow[k] = v;
                arow[k] = v;
            }
        }
    }

    // ================= Phase C: result = attn @ V =============================
    const int dx = tid & 15, qy = tid >> 4;
    const int dc = dx * 4;      // d base (0..60)
    const int qc = qy * 2;      // q base (0..30)
    float oacc[2][4] = {};

    for (int kb = 0; kb < TT / KC; ++kb) {
        __syncthreads();
        const float* Vc = Vb + (size_t)kb * KC * DKK;
        for (int idx = tid; idx < KC * DKK; idx += NTH) {
            int k = idx / DKK, d = idx % DKK;
            st[k * VSTR + d] = Vc[idx];
        }
        __syncthreads();

        const float* srow0 = sc + qc * SSTR + kb * KC;
        const float* srow1 = srow0 + SSTR;
        #pragma unroll 4
        for (int k = 0; k < KC; ++k) {
            float a0 = srow0[k];
            float a1 = srow1[k];
            float4 v = *(const float4*)&st[k * VSTR + dc];
            oacc[0][0] += a0 * v.x; oacc[0][1] += a0 * v.y; oacc[0][2] += a0 * v.z; oacc[0][3] += a0 * v.w;
            oacc[1][0] += a1 * v.x; oacc[1][1] += a1 * v.y; oacc[1][2] += a1 * v.z; oacc[1][3] += a1 * v.w;
        }
    }

    #pragma unroll
    for (int i = 0; i < 2; ++i) {
        float4 wv = make_float4(oacc[i][0], oacc[i][1], oacc[i][2], oacc[i][3]);
        *(float4*)&out[((size_t)b * TT + q0g + qc + i) * DKK + dc] = wv;
    }
}

extern "C" void kernel_launch(void* const* d_in, const int* in_sizes, int n_in,
                              void* d_out, int out_size)
{
    (void)in_sizes; (void)n_in; (void)out_size;
    const float*        Kg  = (const float*)d_in[0];
    const float*        Vg  = (const float*)d_in[1];
    const float*        Qg  = (const float*)d_in[2];
    const unsigned int* Mg  = (const unsigned int*)d_in[3];
    const float*        QMg = (const float*)d_in[4];
    float*              out = (float*)d_out;

    cudaFuncSetAttribute(mha_kernel, cudaFuncAttributeMaxDynamicSharedMemorySize, SMEM_BYTES);

    dim3 grid(BATCH * (TT / QT));   // 1024 blocks
    mha_kernel<<<grid, NTH, SMEM_BYTES>>>(Kg, Vg, Qg, Mg, QMg, out);
}

// round 4
// speedup vs baseline: 1.4534x; 1.4534x over previous
#include <cuda_runtime.h>
#include <cstdint>

#define BATCH 32
#define TT 1024
#define DKK 64
#define QT 32          // queries per block
#define KC 128         // k chunk
#define NTH 512

#define SSTR 1032      // scores row stride (floats)
#define KSTR 132       // transposed K stage stride
#define VSTR 68        // V stage stride
#define QSTR 36        // transposed Q stage stride

#define SC_FLOATS (QT * SSTR)            // 33024
#define ST_OFF    SC_FLOATS
#define ST_FLOATS 8704                   // max(64*132=8448, 128*68=8704)
#define QS_OFF    (ST_OFF + ST_FLOATS)   // 41728
#define QS_FLOATS (DKK * QSTR)           // 2304
#define SMEM_FLOATS (QS_OFF + QS_FLOATS) // 44032
#define SMEM_BYTES  (SMEM_FLOATS * 4)    // 176128

#define RES_FLOATS ((size_t)BATCH * TT * DKK)  // 2097152
#define MASK_FILL_F (-4294967296.0f)           // float32(-2^32+1)

__global__ void __launch_bounds__(NTH, 1)
mha_kernel(const float* __restrict__ Kg,
           const float* __restrict__ Vg,
           const float* __restrict__ Qg,
           const unsigned int* __restrict__ Mg,   // bool as 4-byte: nonzero == True
           const float* __restrict__ QMg,
           float* __restrict__ out)
{
    extern __shared__ float sm[];
    float* sc = sm;             // scores [QT][SSTR]
    float* st = sm + ST_OFF;    // K/V staging
    float* qs = sm + QS_OFF;    // Q transposed [d][q]

    const int tid = threadIdx.x;
    const int b   = blockIdx.x / (TT / QT);
    const int qt  = blockIdx.x % (TT / QT);
    const int q0g = qt * QT;

    const float* Qb = Qg + ((size_t)b * TT + q0g) * DKK;
    const float* Kb = Kg + (size_t)b * TT * DKK;
    const float* Vb = Vg + (size_t)b * TT * DKK;

    // ---- stage Q transposed: qs[d*QSTR + q] ----
    for (int idx = tid; idx < QT * DKK; idx += NTH) {
        int q = idx / DKK, d = idx % DKK;
        qs[d * QSTR + q] = Qb[idx];
    }

    const int tx = tid & 31, ty = tid >> 5;   // ty 0..15

    // ================= Phase A: scores = (Q K^T) * 1/sqrt(DK) =================
    // 16 warps: warp = (qgroup 0..7) x (khalf 0..1). Per thread: 4q x 2k.
    {
        const int qa = (ty & 7) * 4;             // q base
        const int ka = (ty >> 3) * 64 + tx * 2;  // k base within chunk

        for (int kb = 0; kb < TT / KC; ++kb) {
            __syncthreads();
            const float* Kc = Kb + (size_t)kb * KC * DKK;
            for (int idx = tid; idx < KC * DKK; idx += NTH) {
                int k = idx / DKK, d = idx % DKK;
                st[d * KSTR + k] = Kc[idx];      // transpose to [d][k]
            }
            __syncthreads();

            float acc[4][2] = {};
            #pragma unroll
            for (int d = 0; d < DKK; ++d) {
                float4 a  = *(const float4*)&qs[d * QSTR + qa];   // broadcast
                float2 bv = *(const float2*)&st[d * KSTR + ka];
                acc[0][0] += a.x * bv.x; acc[0][1] += a.x * bv.y;
                acc[1][0] += a.y * bv.x; acc[1][1] += a.y * bv.y;
                acc[2][0] += a.z * bv.x; acc[2][1] += a.z * bv.y;
                acc[3][0] += a.w * bv.x; acc[3][1] += a.w * bv.y;
            }
            #pragma unroll
            for (int i = 0; i < 4; ++i) {
                float2 w = make_float2(acc[i][0] * 0.125f, acc[i][1] * 0.125f);
                *(float2*)&sc[(qa + i) * SSTR + kb * KC + ka] = w;
            }
        }
        __syncthreads();
    }

    // ================= Phase B: mask + softmax + query_mask, write attn =======
    // 16 warps x 2 rows. Vectorized: uint4 mask, float4 scores.
    {
        #pragma unroll
        for (int r = 0; r < 2; ++r) {
            const int q  = ty * 2 + r;
            const int qg = q0g + q;
            const uint4* mrow = (const uint4*)(Mg + ((size_t)b * TT + qg) * (size_t)TT);
            float* srow = sc + q * SSTR;

            float mx = -3.402823466e38f;
            #pragma unroll
            for (int it = 0; it < 8; ++it) {
                const int k4 = tx + it * 32;
                uint4  m = mrow[k4];
                float4 s = *(float4*)&srow[k4 * 4];
                if (m.x) s.x = MASK_FILL_F;
                if (m.y) s.y = MASK_FILL_F;
                if (m.z) s.z = MASK_FILL_F;
                if (m.w) s.w = MASK_FILL_F;
                *(float4*)&srow[k4 * 4] = s;
                mx = fmaxf(mx, fmaxf(fmaxf(s.x, s.y), fmaxf(s.z, s.w)));
            }
            #pragma unroll
            for (int o = 16; o; o >>= 1) mx = fmaxf(mx, __shfl_xor_sync(0xffffffffu, mx, o));

            float sum = 0.f;
            #pragma unroll
            for (int it = 0; it < 8; ++it) {
                const int k4 = tx + it * 32;
                float4 s = *(float4*)&srow[k4 * 4];
                s.x = __expf(s.x - mx); s.y = __expf(s.y - mx);
                s.z = __expf(s.z - mx); s.w = __expf(s.w - mx);
                *(float4*)&srow[k4 * 4] = s;
                sum += (s.x + s.y) + (s.z + s.w);
            }
            #pragma unroll
            for (int o = 16; o; o >>= 1) sum += __shfl_xor_sync(0xffffffffu, sum, o);

            const float inv = QMg[(size_t)b * TT + qg] / sum;
            float* arow = out + RES_FLOATS + ((size_t)b * TT + qg) * (size_t)TT;
            #pragma unroll
            for (int it = 0; it < 8; ++it) {
                const int k4 = tx + it * 32;
                float4 s = *(float4*)&srow[k4 * 4];
                s.x *= inv; s.y *= inv; s.z *= inv; s.w *= inv;
                *(float4*)&srow[k4 * 4] = s;
                *(float4*)&arow[k4 * 4] = s;
            }
        }
    }

    // ================= Phase C: result = attn @ V (split-k halves) ============
    // threads [0,256): k even; threads [256,512): k odd. Per thread 2q x 4d.
    const int kh = tid >> 8;            // 0/1
    const int t  = tid & 255;
    const int dc = (t & 15) * 4;        // d base
    const int qc = (t >> 4) * 2;        // q base
    float oacc[2][4] = {};

    for (int kb = 0; kb < TT / KC; ++kb) {
        __syncthreads();
        const float* Vc = Vb + (size_t)kb * KC * DKK;
        for (int idx = tid; idx < KC * DKK; idx += NTH) {
            int k = idx / DKK, d = idx % DKK;
            st[k * VSTR + d] = Vc[idx];
        }
        __syncthreads();

        const float* srow0 = sc + qc * SSTR + kb * KC + kh;
        const float* srow1 = srow0 + SSTR;
        const float* vrow  = st + (size_t)kh * VSTR + dc;
        #pragma unroll 4
        for (int j = 0; j < KC / 2; ++j) {
            float a0 = srow0[2 * j];
            float a1 = srow1[2 * j];
            float4 v = *(const float4*)&vrow[2 * j * VSTR];
            oacc[0][0] += a0 * v.x; oacc[0][1] += a0 * v.y; oacc[0][2] += a0 * v.z; oacc[0][3] += a0 * v.w;
            oacc[1][0] += a1 * v.x; oacc[1][1] += a1 * v.y; oacc[1][2] += a1 * v.z; oacc[1][3] += a1 * v.w;
        }
    }

    // partner reduction through smem (reuse staging area)
    __syncthreads();
    float* red = st;     // 256 threads * 8 floats = 8KB
    if (kh == 1) {
        #pragma unroll
        for (int i = 0; i < 2; ++i) {
            *(float4*)&red[t * 8 + i * 4] = make_float4(oacc[i][0], oacc[i][1], oacc[i][2], oacc[i][3]);
        }
    }
    __syncthreads();
    if (kh == 0) {
        #pragma unroll
        for (int i = 0; i < 2; ++i) {
            float4 p = *(float4*)&red[t * 8 + i * 4];
            float4 wv = make_float4(oacc[i][0] + p.x, oacc[i][1] + p.y,
                                    oacc[i][2] + p.z, oacc[i][3] + p.w);
            *(float4*)&out[((size_t)b * TT + q0g + qc + i) * DKK + dc] = wv;
        }
    }
}

extern "C" void kernel_launch(void* const* d_in, const int* in_sizes, int n_in,
                              void* d_out, int out_size)
{
    (void)in_sizes; (void)n_in; (void)out_size;
    const float*        Kg  = (const float*)d_in[0];
    const float*        Vg  = (const float*)d_in[1];
    const float*        Qg  = (const float*)d_in[2];
    const unsigned int* Mg  = (const unsigned int*)d_in[3];
    const float*        QMg = (const float*)d_in[4];
    float*              out = (float*)d_out;

    cudaFuncSetAttribute(mha_kernel, cudaFuncAttributeMaxDynamicSharedMemorySize, SMEM_BYTES);

    dim3 grid(BATCH * (TT / QT));   // 1024 blocks
    mha_kernel<<<grid, NTH, SMEM_BYTES>>>(Kg, Vg, Qg, Mg, QMg, out);
}

// round 7
// speedup vs baseline: 2.5014x; 1.7211x over previous
#include <cuda_runtime.h>
#include <cstdint>

#define BATCH 32
#define TT 1024
#define DKK 64
#define QT 32          // queries per block
#define KC 128         // k chunk
#define NTH 256

#define KSTR 132       // transposed K stage stride (floats)
#define VSTR 68        // V stage stride
#define QSTR 36        // transposed Q stage stride

// SMEM union (floats):
//   Phase A: [0, 8448)  = K chunk transposed [64][132]
//            [8704, 8704+2304) = Q transposed [64][36]
//   Phase C: [0, 8704)  = V chunk [128][68]
//            [8704, 8704+4096) = attn tile [32][128]
#define STK_OFF 0
#define STV_OFF 0
#define AUX_OFF 8704
#define SMEM_FLOATS 12800
#define SMEM_BYTES  (SMEM_FLOATS * 4)    // 51200 -> 4 CTAs/SM

#define RES_FLOATS ((size_t)BATCH * TT * DKK)  // 2097152
#define MASK_FILL_F (-4294967296.0f)           // float32(-2^32+1)

__global__ void __launch_bounds__(NTH, 4)
mha_kernel(const float* __restrict__ Kg,
           const float* __restrict__ Vg,
           const float* __restrict__ Qg,
           const unsigned int* __restrict__ Mg,   // bool as 4-byte: nonzero == True
           const float* __restrict__ QMg,
           float* __restrict__ out)
{
    extern __shared__ float sm[];
    float* stg = sm + STK_OFF;   // K (A) / V (C) staging
    float* aux = sm + AUX_OFF;   // Q (A) / attn tile (C)

    const int tid = threadIdx.x;
    const int b   = blockIdx.x / (TT / QT);
    const int qt  = blockIdx.x % (TT / QT);
    const int q0g = qt * QT;

    const float* Qb = Qg + ((size_t)b * TT + q0g) * DKK;
    const float* Kb = Kg + (size_t)b * TT * DKK;
    const float* Vb = Vg + (size_t)b * TT * DKK;
    float* attnG = out + RES_FLOATS + ((size_t)b * TT + q0g) * (size_t)TT;  // [32][1024]

    const int tx = tid & 31, ty = tid >> 5;   // ty 0..7

    // ---- stage Q transposed: aux[d*QSTR + q] ----
    for (int idx = tid; idx < QT * DKK; idx += NTH) {
        int q = idx >> 6, d = idx & 63;
        aux[d * QSTR + q] = Qb[idx];
    }

    // ================= Phase A: scores = (Q K^T)/8 -> gmem attn region ========
    // 8 warps, per thread 4q x 4k (warp ty covers q 4ty..4ty+3, tx covers 128 k).
    {
        const int qa = ty * 4;
        const int ka = tx * 4;

        for (int kb = 0; kb < TT / KC; ++kb) {
            __syncthreads();
            const float* Kc = Kb + (size_t)kb * KC * DKK;
            #pragma unroll
            for (int i = 0; i < (KC * DKK) / NTH; ++i) {
                int idx = tid + i * NTH;
                int k = idx >> 6, d = idx & 63;            // lanes: consecutive d
                stg[d * KSTR + k] = Kc[idx];               // coalesced LDG, 4-way STS
            }
            __syncthreads();

            float acc[4][4] = {};
            #pragma unroll
            for (int d = 0; d < DKK; ++d) {
                float4 a  = *(const float4*)&aux[d * QSTR + qa];   // broadcast
                float4 bv = *(const float4*)&stg[d * KSTR + ka];
                acc[0][0] += a.x * bv.x; acc[0][1] += a.x * bv.y; acc[0][2] += a.x * bv.z; acc[0][3] += a.x * bv.w;
                acc[1][0] += a.y * bv.x; acc[1][1] += a.y * bv.y; acc[1][2] += a.y * bv.z; acc[1][3] += a.y * bv.w;
                acc[2][0] += a.z * bv.x; acc[2][1] += a.z * bv.y; acc[2][2] += a.z * bv.z; acc[2][3] += a.z * bv.w;
                acc[3][0] += a.w * bv.x; acc[3][1] += a.w * bv.y; acc[3][2] += a.w * bv.z; acc[3][3] += a.w * bv.w;
            }
            #pragma unroll
            for (int i = 0; i < 4; ++i) {
                float4 w = make_float4(acc[i][0] * 0.125f, acc[i][1] * 0.125f,
                                       acc[i][2] * 0.125f, acc[i][3] * 0.125f);
                *(float4*)&attnG[(size_t)(qa + i) * TT + kb * KC + ka] = w;
            }
        }
    }
    __syncthreads();   // scores visible block-wide; staging buffer free

    // ================= Phase B: mask + softmax + query_mask (registers) =======
    // 8 warps x 4 rows; full row (1024) = 8 float4 per lane.
    {
        #pragma unroll
        for (int r = 0; r < 4; ++r) {
            const int q  = ty * 4 + r;
            const int qg = q0g + q;
            float4* srow = (float4*)(attnG + (size_t)q * TT);
            const uint4* mrow = (const uint4*)(Mg + ((size_t)b * TT + qg) * (size_t)TT);

            float4 s[8];
            float mx = -3.402823466e38f;
            #pragma unroll
            for (int it = 0; it < 8; ++it) {
                const int k4 = tx + it * 32;
                uint4 m = mrow[k4];
                s[it] = srow[k4];
                if (m.x) s[it].x = MASK_FILL_F;
                if (m.y) s[it].y = MASK_FILL_F;
                if (m.z) s[it].z = MASK_FILL_F;
                if (m.w) s[it].w = MASK_FILL_F;
                mx = fmaxf(mx, fmaxf(fmaxf(s[it].x, s[it].y), fmaxf(s[it].z, s[it].w)));
            }
            #pragma unroll
            for (int o = 16; o; o >>= 1) mx = fmaxf(mx, __shfl_xor_sync(0xffffffffu, mx, o));

            float sum = 0.f;
            #pragma unroll
            for (int it = 0; it < 8; ++it) {
                s[it].x = __expf(s[it].x - mx); s[it].y = __expf(s[it].y - mx);
                s[it].z = __expf(s[it].z - mx); s[it].w = __expf(s[it].w - mx);
                sum += (s[it].x + s[it].y) + (s[it].z + s[it].w);
            }
            #pragma unroll
            for (int o = 16; o; o >>= 1) sum += __shfl_xor_sync(0xffffffffu, sum, o);

            const float inv = QMg[(size_t)b * TT + qg] / sum;
            #pragma unroll
            for (int it = 0; it < 8; ++it) {
                s[it].x *= inv; s[it].y *= inv; s[it].z *= inv; s[it].w *= inv;
                srow[tx + it * 32] = s[it];
            }
        }
    }

    // ================= Phase C: result = attn @ V ============================
    // Stage V chunk + attn tile from gmem (L2-hot). Per thread 2q x 4d.
    const int dc = (tid & 15) * 4;
    const int qc = (tid >> 4) * 2;
    float oacc[2][4] = {};

    for (int kb = 0; kb < TT / KC; ++kb) {
        __syncthreads();
        const float4* Vc4 = (const float4*)(Vb + (size_t)kb * KC * DKK);
        #pragma unroll
        for (int i = 0; i < (KC * DKK / 4) / NTH; ++i) {      // 8 iters of float4
            int idx4 = tid + i * NTH;
            float4 v = Vc4[idx4];
            int k = idx4 >> 4, d = (idx4 & 15) << 2;
            *(float4*)&stg[k * VSTR + d] = v;
        }
        #pragma unroll
        for (int i = 0; i < (QT * KC / 4) / NTH; ++i) {       // 4 iters of float4
            int idx4 = tid + i * NTH;
            int q = idx4 >> 5, k4 = idx4 & 31;
            float4 a = *(const float4*)&attnG[(size_t)q * TT + kb * KC + k4 * 4];
            *(float4*)&aux[q * KC + k4 * 4] = a;
        }
        __syncthreads();

        const float* arow0 = aux + qc * KC;
        const float* arow1 = arow0 + KC;
        #pragma unroll 4
        for (int k = 0; k < KC; ++k) {
            float a0 = arow0[k];
            float a1 = arow1[k];
            float4 v = *(const float4*)&stg[k * VSTR + dc];
            oacc[0][0] += a0 * v.x; oacc[0][1] += a0 * v.y; oacc[0][2] += a0 * v.z; oacc[0][3] += a0 * v.w;
            oacc[1][0] += a1 * v.x; oacc[1][1] += a1 * v.y; oacc[1][2] += a1 * v.z; oacc[1][3] += a1 * v.w;
        }
    }

    #pragma unroll
    for (int i = 0; i < 2; ++i) {
        float4 wv = make_float4(oacc[i][0], oacc[i][1], oacc[i][2], oacc[i][3]);
        *(float4*)&out[((size_t)b * TT + q0g + qc + i) * DKK + dc] = wv;
    }
}

extern "C" void kernel_launch(void* const* d_in, const int* in_sizes, int n_in,
                              void* d_out, int out_size)
{
    (void)in_sizes; (void)n_in; (void)out_size;
    const float*        Kg  = (const float*)d_in[0];
    const float*        Vg  = (const float*)d_in[1];
    const float*        Qg  = (const float*)d_in[2];
    const unsigned int* Mg  = (const unsigned int*)d_in[3];
    const float*        QMg = (const float*)d_in[4];
    float*              out = (float*)d_out;

    cudaFuncSetAttribute(mha_kernel, cudaFuncAttributeMaxDynamicSharedMemorySize, SMEM_BYTES);

    dim3 grid(BATCH * (TT / QT));   // 1024 blocks
    mha_kernel<<<grid, NTH, SMEM_BYTES>>>(Kg, Vg, Qg, Mg, QMg, out);
}

// round 9
// speedup vs baseline: 2.5146x; 1.0053x over previous
#include <cuda_runtime.h>
#include <cstdint>

#define BATCH 32
#define TT 1024
#define DKK 64
#define QT 32
#define NTH 256
#define QSTR 36

#define RES_FLOATS ((size_t)BATCH * TT * DKK)  // 2097152
#define MASK_FILL_F (-4294967296.0f)           // float32(-2^32+1)

// 8 MB scratch: K^T stored [b][d][k]
__device__ float KT_dev[(size_t)BATCH * DKK * TT];

// ---------------- transpose K: K[b][k][d] -> KT[b][d][k] ----------------
__global__ void transposeK_kernel(const float* __restrict__ Kg)
{
    __shared__ float t[32][33];
    const int b  = blockIdx.z;
    const int k0 = blockIdx.x * 32;
    const int d0 = blockIdx.y * 32;
    const int x  = threadIdx.x;       // 0..31
    const int y  = threadIdx.y;       // 0..7
    const float* Kb = Kg + ((size_t)b * TT + k0) * DKK + d0;
    #pragma unroll
    for (int i = 0; i < 32; i += 8)
        t[y + i][x] = Kb[(size_t)(y + i) * DKK + x];
    __syncthreads();
    float* KTb = KT_dev + ((size_t)b * DKK + d0) * TT + k0;
    #pragma unroll
    for (int i = 0; i < 32; i += 8)
        KTb[(size_t)(y + i) * TT + x] = t[x][y + i];
}

// ---------------- main fused attention kernel ----------------
__global__ void __launch_bounds__(NTH, 4)
mha_kernel(const float* __restrict__ Vg,
           const float* __restrict__ Qg,
           const unsigned int* __restrict__ Mg,   // bool as 4-byte: nonzero == True
           const float* __restrict__ QMg,
           float* __restrict__ out)
{
    __shared__ float qs[DKK * QSTR];   // 2304 floats; reused as reduction buf in C

    const int tid = threadIdx.x;
    const int tx  = tid & 31, ty = tid >> 5;   // ty 0..7
    const int b   = blockIdx.x >> 5;           // TT/QT = 32 tiles per batch
    const int qt  = blockIdx.x & 31;
    const int q0g = qt * QT;

    const float* Qb  = Qg + ((size_t)b * TT + q0g) * DKK;
    const float* Vb  = Vg + (size_t)b * TT * DKK;
    const float* KTb = KT_dev + (size_t)b * DKK * TT;
    float* attnG = out + RES_FLOATS + ((size_t)b * TT + q0g) * (size_t)TT;  // [32][1024]

    // ---- stage Q transposed: qs[d*QSTR + q] ----
    for (int idx = tid; idx < QT * DKK; idx += NTH) {
        int q = idx >> 6, d = idx & 63;
        qs[d * QSTR + q] = Qb[idx];
    }
    __syncthreads();

    // ========== Phase A: scores = (Q K^T)/8 -> gmem attn region ==========
    // warp = (q-half) x (k-quarter); lanes 4(q-grp) x 8(k-grp); thread 4q x 4k.
    {
        const int qh = ty & 1, kq = ty >> 1;
        const int qb = qh * 16 + (tx >> 3) * 4;   // 0..28
        const int kl = (tx & 7) * 4;              // 0..28 within 32-window

        for (int win = 0; win < 8; ++win) {
            const int k0 = kq * 32 + win * 128 + kl;
            float acc[4][4] = {};
            #pragma unroll 8
            for (int d = 0; d < DKK; ++d) {
                float4 kv = *(const float4*)&KTb[(size_t)d * TT + k0];  // 128B/warp, dedup
                float4 qv = *(const float4*)&qs[d * QSTR + qb];         // 64B/warp
                acc[0][0] += qv.x * kv.x; acc[0][1] += qv.x * kv.y; acc[0][2] += qv.x * kv.z; acc[0][3] += qv.x * kv.w;
                acc[1][0] += qv.y * kv.x; acc[1][1] += qv.y * kv.y; acc[1][2] += qv.y * kv.z; acc[1][3] += qv.y * kv.w;
                acc[2][0] += qv.z * kv.x; acc[2][1] += qv.z * kv.y; acc[2][2] += qv.z * kv.z; acc[2][3] += qv.z * kv.w;
                acc[3][0] += qv.w * kv.x; acc[3][1] += qv.w * kv.y; acc[3][2] += qv.w * kv.z; acc[3][3] += qv.w * kv.w;
            }
            #pragma unroll
            for (int r = 0; r < 4; ++r) {
                float4 w = make_float4(acc[r][0] * 0.125f, acc[r][1] * 0.125f,
                                       acc[r][2] * 0.125f, acc[r][3] * 0.125f);
                *(float4*)&attnG[(size_t)(qb + r) * TT + k0] = w;
            }
        }
    }
    __syncthreads();   // all scores of this CTA's 32 rows visible

    // ========== Phase B: mask + softmax + query_mask (registers) ==========
    {
        #pragma unroll
        for (int r = 0; r < 4; ++r) {
            const int q  = ty * 4 + r;
            const int qg = q0g + q;
            float4* srow = (float4*)(attnG + (size_t)q * TT);
            const uint4* mrow = (const uint4*)(Mg + ((size_t)b * TT + qg) * (size_t)TT);

            float4 s[8];
            float mx = -3.402823466e38f;
            #pragma unroll
            for (int it = 0; it < 8; ++it) {
                const int k4 = tx + it * 32;
                uint4 m = mrow[k4];
                s[it] = srow[k4];
                if (m.x) s[it].x = MASK_FILL_F;
                if (m.y) s[it].y = MASK_FILL_F;
                if (m.z) s[it].z = MASK_FILL_F;
                if (m.w) s[it].w = MASK_FILL_F;
                mx = fmaxf(mx, fmaxf(fmaxf(s[it].x, s[it].y), fmaxf(s[it].z, s[it].w)));
            }
            #pragma unroll
            for (int o = 16; o; o >>= 1) mx = fmaxf(mx, __shfl_xor_sync(0xffffffffu, mx, o));

            float sum = 0.f;
            #pragma unroll
            for (int it = 0; it < 8; ++it) {
                s[it].x = __expf(s[it].x - mx); s[it].y = __expf(s[it].y - mx);
                s[it].z = __expf(s[it].z - mx); s[it].w = __expf(s[it].w - mx);
                sum += (s[it].x + s[it].y) + (s[it].z + s[it].w);
            }
            #pragma unroll
            for (int o = 16; o; o >>= 1) sum += __shfl_xor_sync(0xffffffffu, sum, o);

            const float inv = QMg[(size_t)b * TT + qg] / sum;
            #pragma unroll
            for (int it = 0; it < 8; ++it) {
                s[it].x *= inv; s[it].y *= inv; s[it].z *= inv; s[it].w *= inv;
                srow[tx + it * 32] = s[it];
            }
        }
    }
    __syncthreads();   // attn rows final

    // ========== Phase C: result = attn @ V, direct gmem (L2-hot) ==========
    // warp = (q-half) x (d-half) x (k-half); lanes 4(q-grp) x 8(d-grp); thread 4q x 4d.
    {
        const int qh = ty & 1, dh = (ty >> 1) & 1, kh = ty >> 2;
        const int qb = qh * 16 + (tx >> 3) * 4;
        const int dl = dh * 32 + (tx & 7) * 4;
        float acc[4][4] = {};

        const int kbeg = kh * 512, kend = kbeg + 512;
        #pragma unroll 2
        for (int k = kbeg; k < kend; k += 4) {
            float4 a0 = *(const float4*)&attnG[(size_t)(qb + 0) * TT + k];
            float4 a1 = *(const float4*)&attnG[(size_t)(qb + 1) * TT + k];
            float4 a2 = *(const float4*)&attnG[(size_t)(qb + 2) * TT + k];
            float4 a3 = *(const float4*)&attnG[(size_t)(qb + 3) * TT + k];

            float4 v0 = *(const float4*)&Vb[(size_t)(k + 0) * DKK + dl];
            float4 v1 = *(const float4*)&Vb[(size_t)(k + 1) * DKK + dl];
            float4 v2 = *(const float4*)&Vb[(size_t)(k + 2) * DKK + dl];
            float4 v3 = *(const float4*)&Vb[(size_t)(k + 3) * DKK + dl];

            acc[0][0] += a0.x*v0.x + a0.y*v1.x + a0.z*v2.x + a0.w*v3.x;
            acc[0][1] += a0.x*v0.y + a0.y*v1.y + a0.z*v2.y + a0.w*v3.y;
            acc[0][2] += a0.x*v0.z + a0.y*v1.z + a0.z*v2.z + a0.w*v3.z;
            acc[0][3] += a0.x*v0.w + a0.y*v1.w + a0.z*v2.w + a0.w*v3.w;

            acc[1][0] += a1.x*v0.x + a1.y*v1.x + a1.z*v2.x + a1.w*v3.x;
            acc[1][1] += a1.x*v0.y + a1.y*v1.y + a1.z*v2.y + a1.w*v3.y;
            acc[1][2] += a1.x*v0.z + a1.y*v1.z + a1.z*v2.z + a1.w*v3.z;
            acc[1][3] += a1.x*v0.w + a1.y*v1.w + a1.z*v2.w + a1.w*v3.w;

            acc[2][0] += a2.x*v0.x + a2.y*v1.x + a2.z*v2.x + a2.w*v3.x;
            acc[2][1] += a2.x*v0.y + a2.y*v1.y + a2.z*v2.y + a2.w*v3.y;
            acc[2][2] += a2.x*v0.z + a2.y*v1.z + a2.z*v2.z + a2.w*v3.z;
            acc[2][3] += a2.x*v0.w + a2.y*v1.w + a2.z*v2.w + a2.w*v3.w;

            acc[3][0] += a3.x*v0.x + a3.y*v1.x + a3.z*v2.x + a3.w*v3.x;
            acc[3][1] += a3.x*v0.y + a3.y*v1.y + a3.z*v2.y + a3.w*v3.y;
            acc[3][2] += a3.x*v0.z + a3.y*v1.z + a3.z*v2.z + a3.w*v3.z;
            acc[3][3] += a3.x*v0.w + a3.y*v1.w + a3.z*v2.w + a3.w*v3.w;
        }

        // k-half partner reduction through smem (reuse qs: 2048 <= 2304 floats)
        __syncthreads();
        float* red = qs;
        const int t = tid & 127;     // partner index (same qh,dh,qb,dl)
        if (kh == 1) {
            #pragma unroll
            for (int r = 0; r < 4; ++r)
                *(float4*)&red[t * 16 + r * 4] =
                    make_float4(acc[r][0], acc[r][1], acc[r][2], acc[r][3]);
        }
        __syncthreads();
        if (kh == 0) {
            #pragma unroll
            for (int r = 0; r < 4; ++r) {
                float4 p = *(float4*)&red[t * 16 + r * 4];
                float4 wv = make_float4(acc[r][0] + p.x, acc[r][1] + p.y,
                                        acc[r][2] + p.z, acc[r][3] + p.w);
                *(float4*)&out[((size_t)b * TT + q0g + qb + r) * DKK + dl] = wv;
            }
        }
    }
}

extern "C" void kernel_launch(void* const* d_in, const int* in_sizes, int n_in,
                              void* d_out, int out_size)
{
    (void)in_sizes; (void)n_in; (void)out_size;
    const float*        Kg  = (const float*)d_in[0];
    const float*        Vg  = (const float*)d_in[1];
    const float*        Qg  = (const float*)d_in[2];
    const unsigned int* Mg  = (const unsigned int*)d_in[3];
    const float*        QMg = (const float*)d_in[4];
    float*              out = (float*)d_out;

    dim3 tgrid(TT / 32, DKK / 32, BATCH);       // 32 x 2 x 32
    transposeK_kernel<<<tgrid, dim3(32, 8)>>>(Kg);

    dim3 grid(BATCH * (TT / QT));               // 1024 blocks
    mha_kernel<<<grid, NTH>>>(Vg, Qg, Mg, QMg, out);
}